// round 10
// baseline (speedup 1.0000x reference)
#include <cuda_runtime.h>
#include <math.h>

// out[b,i,j] = pos_biases[j - i + n - 1]
//            + ts_w[ clamp( floor( log(clip(|f32(t[min(i+1,n-1)]) - f32(t[j])|, 1, 1e9)) / 0.301 ), 0, nb ) ]
//
// R6 core (measured best: MUFU path + k-indexed fused table, tight index
// clustering -> low LDS conflicts), restructured for minimum overhead:
// one pass per block (each thread owns 8 consecutive j), no inner j-loop,
// no per-row predicates (i0 clamped), pos window in 16 registers.
// thr[k] = smallest f32 x with floor(fdiv_rn(log_rn(x),0.301f)) >= k
// (host-built, ulp-exact, by-value param). rel_err identical to R3-R8.

struct ThrTab { float thr[80]; };

__global__ void __launch_bounds__(256)
bias_kernel(const int*   __restrict__ ts,
            const float* __restrict__ pos,
            const float* __restrict__ tsw,
            float*       __restrict__ out,
            int n, int nb, ThrTab tab) {
    extern __shared__ float sm[];
    float4* s_tab = (float4*)sm;              // 80 x (thr[k], w[k-1], w[k], 0)
    float*  s_pos = sm + 320;                 // n + 16 floats

    const int b   = blockIdx.y;
    int i0 = blockIdx.x * 8;
    if (i0 > n - 8) i0 = n - 8;               // clamp: duplicate rows write identical data
    const int tid = threadIdx.x;
    const int* trow = ts + (size_t)b * n;

    if (tid < 80) {
        int k = tid;
        float wkm1 = tsw[min(max(k - 1, 0), nb)];
        float wk   = tsw[min(k, nb)];
        s_tab[k] = make_float4(tab.thr[k], wkm1, wk, 0.0f);
    }
    const int pbase = n - 8 - i0;             // >= 0
    for (int idx = tid; idx < n + 16; idx += 256) {
        int g = pbase + idx;
        s_pos[idx] = (g <= 2 * n - 2) ? pos[g] : 0.0f;
    }
    __syncthreads();

    float tnr[8];
    #pragma unroll
    for (int r = 0; r < 8; ++r) tnr[r] = (float)__ldg(&trow[min(i0 + r + 1, n - 1)]);

    const int j0 = tid * 8;                   // 256 threads x 8 j = full row (n = 2048)
    if (j0 >= n) return;

    int4 ti0 = *reinterpret_cast<const int4*>(trow + j0);
    int4 ti1 = *reinterpret_cast<const int4*>(trow + j0 + 4);
    const float tv[8] = {(float)ti0.x, (float)ti0.y, (float)ti0.z, (float)ti0.w,
                         (float)ti1.x, (float)ti1.y, (float)ti1.z, (float)ti1.w};

    float4 p0 = *reinterpret_cast<const float4*>(s_pos + j0);
    float4 p1 = *reinterpret_cast<const float4*>(s_pos + j0 + 4);
    float4 p2 = *reinterpret_cast<const float4*>(s_pos + j0 + 8);
    float4 p3 = *reinterpret_cast<const float4*>(s_pos + j0 + 12);
    const float pw[16] = {p0.x, p0.y, p0.z, p0.w,  p1.x, p1.y, p1.z, p1.w,
                          p2.x, p2.y, p2.z, p2.w,  p3.x, p3.y, p3.z, p3.w};

    float* op = out + ((size_t)b * n + i0) * (size_t)n + j0;

    #pragma unroll
    for (int r = 0; r < 8; ++r) {
        const float tn = tnr[r];
        float w[8];
        #pragma unroll
        for (int e = 0; e < 8; ++e) {
            float x = fmaxf(fabsf(tn - tv[e]), 1.0f);
            float q = fmaf(__log2f(x), 2.3028145f, 1.25e-4f);  // ln2/0.301, +eps
            float4 te = s_tab[(int)q];                          // k_ref or k_ref+1
            w[e] = (x < te.x) ? te.y : te.z;                    // exact select
        }
        float4 oa, ob;
        oa.x = w[0] + pw[7 - r];
        oa.y = w[1] + pw[8 - r];
        oa.z = w[2] + pw[9 - r];
        oa.w = w[3] + pw[10 - r];
        ob.x = w[4] + pw[11 - r];
        ob.y = w[5] + pw[12 - r];
        ob.z = w[6] + pw[13 - r];
        ob.w = w[7] + pw[14 - r];
        *reinterpret_cast<float4*>(op)     = oa;
        *reinterpret_cast<float4*>(op + 4) = ob;
        op += n;
    }
}

static void build_thresholds_host(ThrTab* tab) {
    typedef union { float f; unsigned u; } FU;
    for (int k = 0; k < 80; ++k) {
        if (k == 0) { tab->thr[0] = 1.0f; continue; }
        volatile float kb = 0.301f;                  // force f32 division semantics
        FU l; l.f = (float)(0.301 * (double)k);
        while (!((float)(l.f / kb) >= (float)k)) l.u += 1u;
        for (;;) {
            FU p; p.u = l.u - 1u;
            if ((float)(p.f / kb) >= (float)k) l.u = p.u; else break;
        }
        FU x; x.f = (float)exp((double)l.f);
        while (!((float)log((double)x.f) >= l.f)) x.u += 1u;
        for (;;) {
            FU p; p.u = x.u - 1u;
            if ((float)log((double)p.f) >= l.f) x.u = p.u; else break;
        }
        tab->thr[k] = x.f;
    }
}

extern "C" void kernel_launch(void* const* d_in, const int* in_sizes, int n_in,
                              void* d_out, int out_size) {
    const int*   ts  = (const int*)d_in[0];     // timestamps (B*N) int32
    const float* pos = (const float*)d_in[1];   // pos_biases (2N-1) f32
    const float* tsw = (const float*)d_in[2];   // ts_w (nb+1) f32

    const int n  = (in_sizes[1] + 1) / 2;
    const int B  = in_sizes[0] / n;
    const int nb = in_sizes[2] - 1;

    ThrTab tab;
    build_thresholds_host(&tab);

    size_t smem = (size_t)(320 + n + 16) * sizeof(float);
    dim3 grid((n + 7) / 8, B);
    bias_kernel<<<grid, 256, smem>>>(ts, pos, tsw, (float*)d_out, n, nb, tab);
}

// round 11
// speedup vs baseline: 1.2700x; 1.2700x over previous
#include <cuda_runtime.h>
#include <math.h>

// out[b,i,j] = pos_biases[j - i + n - 1]
//            + ts_w[ clamp( floor( log(clip(|f32(t[min(i+1,n-1)]) - f32(t[j])|, 1, 1e9)) / 0.301 ), 0, nb ) ]
//
// R6 core + VERTICAL coherence: for a fixed column j, the 8 row-anchors span
// ~8 timestamps while bucket runs at distance |dt| are ~0.7|dt| wide, so all
// 8 rows share one exact bucket whenever |i-j| >~ 10 (~99% of elements).
// Exact test: d_r monotone in r; same sign(d0,d7) => |d_r| in [xlo,xhi];
// one biased-trunc log + fused table (thr[k], w[k-1], w[k], thr[k+1]) gives
// xlo's exact bucket and run upper bound; xhi < bound => 1 weight / 8 rows.
// Fallback = bit-identical R6 per-element chain. rel_err 4.933e-4 unchanged.

struct ThrTab { float thr[81]; };

__global__ void __launch_bounds__(256)
bias_kernel(const int*   __restrict__ ts,
            const float* __restrict__ pos,
            const float* __restrict__ tsw,
            float*       __restrict__ out,
            int n, int nb, ThrTab tab) {
    extern __shared__ float sm[];
    float4* s_tab = (float4*)sm;              // 80 x (thr[k], w[k-1], w[k], thr[k+1])
    float*  s_pos = sm + 320;                 // n + 16 floats

    const int b   = blockIdx.y;
    const int i0  = blockIdx.x * 8;
    const int tid = threadIdx.x;
    const int* trow = ts + (size_t)b * n;

    if (tid < 80) {
        int k = tid;
        float wkm1 = tsw[min(max(k - 1, 0), nb)];
        float wk   = tsw[min(k, nb)];
        s_tab[k] = make_float4(tab.thr[k], wkm1, wk, tab.thr[k + 1]);
    }
    const int pbase = n - 8 - i0;
    for (int idx = tid; idx < n + 16; idx += 256) {
        int g = pbase + idx;
        s_pos[idx] = (g >= 0 && g <= 2 * n - 2) ? pos[g] : 0.0f;
    }
    __syncthreads();

    float tnr[8];
    #pragma unroll
    for (int r = 0; r < 8; ++r) tnr[r] = (float)__ldg(&trow[min(i0 + r + 1, n - 1)]);
    const float tn0 = tnr[0];
    const float tn7 = tnr[7];

    const bool full = (i0 + 8 <= n);
    float* oblk = out + ((size_t)b * n + i0) * (size_t)n;

    for (int jj = tid * 4; jj < n; jj += 1024) {
        int4 ti = *reinterpret_cast<const int4*>(trow + jj);
        const float tv[4] = {(float)ti.x, (float)ti.y, (float)ti.z, (float)ti.w};
        float4 p0 = *reinterpret_cast<const float4*>(s_pos + jj);
        float4 p1 = *reinterpret_cast<const float4*>(s_pos + jj + 4);
        float4 p2 = *reinterpret_cast<const float4*>(s_pos + jj + 8);
        const float pw[12] = {p0.x, p0.y, p0.z, p0.w,
                              p1.x, p1.y, p1.z, p1.w,
                              p2.x, p2.y, p2.z, p2.w};
        float* op = oblk + jj;

        // vertical coherence probe: one bucket chain per column
        float wc[4];
        bool coh = true;
        #pragma unroll
        for (int e = 0; e < 4; ++e) {
            float dlo = tn0 - tv[e];
            float dhi = tn7 - tv[e];
            float alo = fmaxf(fabsf(dlo), 1.0f);
            float ahi = fmaxf(fabsf(dhi), 1.0f);
            float xlo = fminf(alo, ahi);
            float xhi = fmaxf(alo, ahi);
            float q = fmaf(__log2f(xlo), 2.3028145f, 1.25e-4f);
            float4 te = s_tab[(int)q];
            bool inlo = (xlo >= te.x);
            wc[e] = inlo ? te.z : te.y;
            float hb = inlo ? te.w : te.x;            // exclusive run upper bound
            bool same = ((__float_as_int(dlo) ^ __float_as_int(dhi)) >= 0);
            coh = coh && same && (xhi < hb);
        }

        if (coh) {
            #pragma unroll
            for (int r = 0; r < 8; ++r) {
                if (full || i0 + r < n) {
                    float4 o;
                    o.x = wc[0] + pw[7 - r];
                    o.y = wc[1] + pw[8 - r];
                    o.z = wc[2] + pw[9 - r];
                    o.w = wc[3] + pw[10 - r];
                    *reinterpret_cast<float4*>(op) = o;
                }
                op += n;
            }
        } else {
            #pragma unroll
            for (int r = 0; r < 8; ++r) {
                const float tn = tnr[r];
                float w[4];
                #pragma unroll
                for (int e = 0; e < 4; ++e) {
                    float x = fmaxf(fabsf(tn - tv[e]), 1.0f);
                    float q = fmaf(__log2f(x), 2.3028145f, 1.25e-4f);
                    float4 te = s_tab[(int)q];
                    w[e] = (x < te.x) ? te.y : te.z;
                }
                if (full || i0 + r < n) {
                    float4 o;
                    o.x = w[0] + pw[7 - r];
                    o.y = w[1] + pw[8 - r];
                    o.z = w[2] + pw[9 - r];
                    o.w = w[3] + pw[10 - r];
                    *reinterpret_cast<float4*>(op) = o;
                }
                op += n;
            }
        }
    }
}

static void build_thresholds_host(ThrTab* tab) {
    typedef union { float f; unsigned u; } FU;
    for (int k = 0; k < 81; ++k) {
        if (k == 0) { tab->thr[0] = 1.0f; continue; }
        volatile float kb = 0.301f;                  // force f32 division semantics
        FU l; l.f = (float)(0.301 * (double)k);
        while (!((float)(l.f / kb) >= (float)k)) l.u += 1u;
        for (;;) {
            FU p; p.u = l.u - 1u;
            if ((float)(p.f / kb) >= (float)k) l.u = p.u; else break;
        }
        FU x; x.f = (float)exp((double)l.f);
        while (!((float)log((double)x.f) >= l.f)) x.u += 1u;
        for (;;) {
            FU p; p.u = x.u - 1u;
            if ((float)log((double)p.f) >= l.f) x.u = p.u; else break;
        }
        tab->thr[k] = x.f;
    }
}

extern "C" void kernel_launch(void* const* d_in, const int* in_sizes, int n_in,
                              void* d_out, int out_size) {
    const int*   ts  = (const int*)d_in[0];     // timestamps (B*N) int32
    const float* pos = (const float*)d_in[1];   // pos_biases (2N-1) f32
    const float* tsw = (const float*)d_in[2];   // ts_w (nb+1) f32

    const int n  = (in_sizes[1] + 1) / 2;
    const int B  = in_sizes[0] / n;
    const int nb = in_sizes[2] - 1;

    ThrTab tab;
    build_thresholds_host(&tab);

    size_t smem = (size_t)(320 + n + 16) * sizeof(float);
    dim3 grid((n + 7) / 8, B);
    bias_kernel<<<grid, 256, smem>>>(ts, pos, tsw, (float*)d_out, n, nb, tab);
}